// round 8
// baseline (speedup 1.0000x reference)
#include <cuda_runtime.h>
#include <cstdint>

#define THREADS 256
#define KDIM 120
#define INP 512
#define NPAIR 13
#define KC 24
#define NCHUNK 5
#define NJ2 12
#define X_STRIDE 1028                        // proven conflict-free plane layout

#define PLANE (NJ2 * X_STRIDE)               // 12336 floats per buffer
#define SCR_STRIDE 27                        // routing scratch aliases buffers
#define RED_OFF (2 * PLANE)                  // 24672
#define RAW_OFF (RED_OFF + 8 * 26)
#define OUT_OFF (RAW_OFF + 32)
#define SMEM_FLOATS (OUT_OFF + 32)           // 24944
#define SMEM_BYTES (SMEM_FLOATS * 4)         // 99776

typedef unsigned long long ull;

// W packed [120][26] floats (col 25 = 0): 780 ulonglong2.
// j2-block g: indices g*13 .. g*13+12 -> {k0 pairs 0..12 (ull .x/.y lanes), then k1}
__constant__ ulonglong2 cW2[780];            // zero-init; pad lanes never written

__device__ __forceinline__ ull dup2(float v) {
    ull r;
    asm("mov.b64 %0, {%1, %1};" : "=l"(r) : "r"(__float_as_uint(v)));
    return r;
}
__device__ __forceinline__ void ffma2(ull& d, ull a, ull b) {
    asm("fma.rn.f32x2 %0, %1, %2, %0;" : "+l"(d) : "l"(a), "l"(b));
}
__device__ __forceinline__ void unpack2(ull v, float& lo, float& hi) {
    unsigned int a, b2;
    asm("mov.b64 {%0, %1}, %2;" : "=r"(a), "=r"(b2) : "l"(v));
    lo = __uint_as_float(a);
    hi = __uint_as_float(b2);
}

extern __shared__ float smem[];

__global__ void __launch_bounds__(THREADS, 2)
caps_kernel(const float* __restrict__ x, float* __restrict__ out)
{
    const int b = blockIdx.x;
    const int t = threadIdx.x;
    const int lane = t & 31, g = t >> 5;

    float* scratch = smem;                 // routing partials alias plane buffers
    float* red     = smem + RED_OFF;       // [8][26]
    float* raw     = smem + RAW_OFF;       // [25]
    float* sOut    = smem + OUT_OFF;       // [25]

    ull acc[2][NPAIR];
    #pragma unroll
    for (int r = 0; r < 2; r++)
        #pragma unroll
        for (int p = 0; p < NPAIR; p++) acc[r][p] = 0ull;

    const float4* xg = reinterpret_cast<const float4*>(x) + (size_t)b * (INP * KDIM / 4);

    // per-thread staging slot geometry (constant across chunks)
    // it2 i: idx = t + i*256, row = idx/6, slot = idx%6 -> plane rows 2slot, 2slot+1
    int srow[12], sslot[12];
    #pragma unroll
    for (int i = 0; i < 12; i++) {
        int idx = t + i * THREADS;
        srow[i]  = idx / (KC / 4);
        sslot[i] = idx % (KC / 4);
    }

    // ---- stage chunk 0 into buffer 0 ----
    #pragma unroll
    for (int i = 0; i < 12; i++) {
        float4 v = xg[srow[i] * (KDIM / 4) + sslot[i]];
        float* p0 = smem + (2 * sslot[i]) * X_STRIDE + (srow[i] >> 1) * 4 + (srow[i] & 1) * 2;
        *reinterpret_cast<float2*>(p0)            = make_float2(v.x, v.y);
        *reinterpret_cast<float2*>(p0 + X_STRIDE) = make_float2(v.z, v.w);
    }
    __syncthreads();

    // ---- pipelined chunks: compute kc from cur while prefetching kc+1 into nxt ----
    for (int kc = 0; kc < NCHUNK; kc++) {
        float* cur = smem + (kc & 1) * PLANE;
        float* nxt = smem + ((kc + 1) & 1) * PLANE;
        const ulonglong2* wb = cW2 + kc * NJ2 * NPAIR;
        const int nq = (kc + 1) * (KC / 4);
        const bool pf = (kc < NCHUNK - 1);

        float4 va[6];
        if (pf) {
            #pragma unroll
            for (int i = 0; i < 6; i++)
                va[i] = xg[srow[i] * (KDIM / 4) + nq + sslot[i]];
        }

        // compute j2 = 0..5
        #pragma unroll
        for (int j2 = 0; j2 < 6; j2++) {
            float4 xv = *reinterpret_cast<const float4*>(cur + j2 * X_STRIDE + t * 4);
            ull a0 = dup2(xv.x), a1 = dup2(xv.y), b0 = dup2(xv.z), b1 = dup2(xv.w);
            const ulonglong2* wq = wb + j2 * NPAIR;
            #pragma unroll
            for (int q = 0; q < 6; q++) {
                ulonglong2 v = wq[q];
                ffma2(acc[0][2 * q],     a0, v.x);
                ffma2(acc[1][2 * q],     b0, v.x);
                ffma2(acc[0][2 * q + 1], a0, v.y);
                ffma2(acc[1][2 * q + 1], b0, v.y);
            }
            { ulonglong2 v = wq[6];
              ffma2(acc[0][12], a0, v.x); ffma2(acc[1][12], b0, v.x);
              ffma2(acc[0][0],  a1, v.y); ffma2(acc[1][0],  b1, v.y); }
            #pragma unroll
            for (int q = 7; q < 13; q++) {
                ulonglong2 v = wq[q];
                ffma2(acc[0][2 * q - 13], a1, v.x);
                ffma2(acc[1][2 * q - 13], b1, v.x);
                ffma2(acc[0][2 * q - 12], a1, v.y);
                ffma2(acc[1][2 * q - 12], b1, v.y);
            }
        }

        float4 vb[6];
        if (pf) {
            #pragma unroll
            for (int i = 0; i < 6; i++) {
                float* p0 = nxt + (2 * sslot[i]) * X_STRIDE + (srow[i] >> 1) * 4 + (srow[i] & 1) * 2;
                *reinterpret_cast<float2*>(p0)            = make_float2(va[i].x, va[i].y);
                *reinterpret_cast<float2*>(p0 + X_STRIDE) = make_float2(va[i].z, va[i].w);
            }
            #pragma unroll
            for (int i = 0; i < 6; i++)
                vb[i] = xg[srow[i + 6] * (KDIM / 4) + nq + sslot[i + 6]];
        }

        // compute j2 = 6..11
        #pragma unroll
        for (int j2 = 6; j2 < 12; j2++) {
            float4 xv = *reinterpret_cast<const float4*>(cur + j2 * X_STRIDE + t * 4);
            ull a0 = dup2(xv.x), a1 = dup2(xv.y), b0 = dup2(xv.z), b1 = dup2(xv.w);
            const ulonglong2* wq = wb + j2 * NPAIR;
            #pragma unroll
            for (int q = 0; q < 6; q++) {
                ulonglong2 v = wq[q];
                ffma2(acc[0][2 * q],     a0, v.x);
                ffma2(acc[1][2 * q],     b0, v.x);
                ffma2(acc[0][2 * q + 1], a0, v.y);
                ffma2(acc[1][2 * q + 1], b0, v.y);
            }
            { ulonglong2 v = wq[6];
              ffma2(acc[0][12], a0, v.x); ffma2(acc[1][12], b0, v.x);
              ffma2(acc[0][0],  a1, v.y); ffma2(acc[1][0],  b1, v.y); }
            #pragma unroll
            for (int q = 7; q < 13; q++) {
                ulonglong2 v = wq[q];
                ffma2(acc[0][2 * q - 13], a1, v.x);
                ffma2(acc[1][2 * q - 13], b1, v.x);
                ffma2(acc[0][2 * q - 12], a1, v.y);
                ffma2(acc[1][2 * q - 12], b1, v.y);
            }
        }

        if (pf) {
            #pragma unroll
            for (int i = 0; i < 6; i++) {
                float* p0 = nxt + (2 * sslot[i + 6]) * X_STRIDE + (srow[i + 6] >> 1) * 4 + (srow[i + 6] & 1) * 2;
                *reinterpret_cast<float2*>(p0)            = make_float2(vb[i].x, vb[i].y);
                *reinterpret_cast<float2*>(p0 + X_STRIDE) = make_float2(vb[i].z, vb[i].w);
            }
        }
        __syncthreads();
    }

    // ---- unpack u_hat ----
    float u[2][26];
    #pragma unroll
    for (int r = 0; r < 2; r++)
        #pragma unroll
        for (int p = 0; p < NPAIR; p++)
            unpack2(acc[r][p], u[r][2 * p], u[r][2 * p + 1]);

    float bb[2][5];
    #pragma unroll
    for (int r = 0; r < 2; r++)
        #pragma unroll
        for (int i = 0; i < 5; i++) bb[r][i] = 0.f;

    // ---- 4 routing iterations (verbatim from validated kernel) ----
    for (int it = 0; it < 4; it++) {
        float cw[2][5];
        #pragma unroll
        for (int r = 0; r < 2; r++) {
            float m = bb[r][0];
            #pragma unroll
            for (int i = 1; i < 5; i++) m = fmaxf(m, bb[r][i]);
            float e[5], s = 0.f;
            #pragma unroll
            for (int i = 0; i < 5; i++) { e[i] = __expf(bb[r][i] - m); s += e[i]; }
            float inv = 1.f / s;
            #pragma unroll
            for (int i = 0; i < 5; i++) cw[r][i] = e[i] * inv;
        }
        #pragma unroll
        for (int c = 0; c < 25; c++)
            scratch[t * SCR_STRIDE + c] = cw[0][c / 5] * u[0][c] + cw[1][c / 5] * u[1][c];
        __syncthreads();
        if (lane < 25) {
            float s = 0.f;
            #pragma unroll
            for (int uu = 0; uu < 32; uu++) s += scratch[(g * 32 + uu) * SCR_STRIDE + lane];
            red[g * 26 + lane] = s;
        }
        __syncthreads();
        if (t < 25) {
            float s = 0.f;
            #pragma unroll
            for (int gg = 0; gg < 8; gg++) s += red[gg * 26 + t];
            raw[t] = s;
        }
        __syncthreads();
        if (t < 25) {
            int i5 = (t / 5) * 5;
            float sq = 0.f;
            #pragma unroll
            for (int k = 0; k < 5; k++) { float v = raw[i5 + k]; sq += v * v; }
            sOut[t] = raw[t] * rsqrtf(sq + 1e-7f);   // squash = pure norm-normalization
        }
        __syncthreads();
        if (it < 3) {
            float ov[25];
            #pragma unroll
            for (int c = 0; c < 25; c++) ov[c] = sOut[c];
            #pragma unroll
            for (int r = 0; r < 2; r++)
                #pragma unroll
                for (int i = 0; i < 5; i++) {
                    float s = 0.f;
                    #pragma unroll
                    for (int k = 0; k < 5; k++) s += ov[i * 5 + k] * u[r][i * 5 + k];
                    bb[r][i] = s;   // b REPLACED each iteration (matches reference)
                }
        }
    }

    if (t < 25) out[b * 25 + t] = sOut[t];
}

extern "C" void kernel_launch(void* const* d_in, const int* in_sizes, int n_in,
                              void* d_out, int out_size)
{
    const float* x = (const float*)d_in[0];
    const float* W = (const float*)d_in[1];
    float* out = (float*)d_out;

    // Pack W[120][25] -> constant [120][26] floats (col 25 stays 0 from static init).
    void* csym = nullptr;
    cudaGetSymbolAddress(&csym, cW2);
    cudaMemcpy2DAsync(csym, 26 * sizeof(float),
                      W, 25 * sizeof(float),
                      25 * sizeof(float), KDIM,
                      cudaMemcpyDeviceToDevice, 0);

    cudaFuncSetAttribute(caps_kernel, cudaFuncAttributeMaxDynamicSharedMemorySize, SMEM_BYTES);
    caps_kernel<<<1024, THREADS, SMEM_BYTES>>>(x, out);
}

// round 9
// speedup vs baseline: 1.1887x; 1.1887x over previous
#include <cuda_runtime.h>
#include <cstdint>

#define THREADS 256
#define KDIM 120
#define INP 512
#define NPAIR 13
#define KC 24
#define NCHUNK 5
#define NJ2 12
#define X_STRIDE 1028                        // proven conflict-free plane layout

#define SX_FLOATS (NJ2 * X_STRIDE)           // 12336
#define SCR_STRIDE 27                        // routing scratch aliases sX only
#define SW_OFF SX_FLOATS                     // sW: 60 blocks x 5 ulonglong2 = 1200 floats
#define NSMEMQ 5
#define SW_FLOATS (NCHUNK * NJ2 * NSMEMQ * 4)   // 1200
#define RED_OFF (SW_OFF + SW_FLOATS)         // 13536
#define RAW_OFF (RED_OFF + 8 * 26)
#define OUT_OFF (RAW_OFF + 32)
#define SMEM_FLOATS (OUT_OFF + 32)           // 13808
#define SMEM_BYTES (SMEM_FLOATS * 4)         // 55232

typedef unsigned long long ull;

// W packed [120][26] floats (col 25 = 0): 780 ulonglong2.
// j2-block g: cW2[g*13+q]; q=0..5: k0 pairs (2q,2q+1); q=6: {k0 pair12, k1 pair0};
// q=7..12: k1 pairs (2q-13, 2q-12).
__constant__ ulonglong2 cW2[780];            // zero-init; pad lanes never written

__device__ __forceinline__ ull dup2(float v) {
    ull r;
    asm("mov.b64 %0, {%1, %1};" : "=l"(r) : "r"(__float_as_uint(v)));
    return r;
}
__device__ __forceinline__ void ffma2(ull& d, ull a, ull b) {
    asm("fma.rn.f32x2 %0, %1, %2, %0;" : "+l"(d) : "l"(a), "l"(b));
}
__device__ __forceinline__ void unpack2(ull v, float& lo, float& hi) {
    unsigned int a, b2;
    asm("mov.b64 {%0, %1}, %2;" : "=r"(a), "=r"(b2) : "l"(v));
    lo = __uint_as_float(a);
    hi = __uint_as_float(b2);
}

extern __shared__ float smem[];

__global__ void __launch_bounds__(THREADS, 2)
caps_kernel(const float* __restrict__ x, float* __restrict__ out)
{
    const int b = blockIdx.x;
    const int t = threadIdx.x;
    const int lane = t & 31, g = t >> 5;

    float* sX      = smem;                 // [NJ2][X_STRIDE]
    float* scratch = smem;                 // routing partials alias sX (6912 < 12336)
    ulonglong2* sWq = reinterpret_cast<ulonglong2*>(smem + SW_OFF);  // [60][5]
    float* red     = smem + RED_OFF;       // [8][26]
    float* raw     = smem + RAW_OFF;       // [25]
    float* sOut    = smem + OUT_OFF;       // [25]

    // ---- stage sW: duplicate q-slots 0..4 of every j2-block from constant ----
    for (int idx = t; idx < NCHUNK * NJ2 * NSMEMQ; idx += THREADS) {
        int blk = idx / NSMEMQ, q = idx % NSMEMQ;
        sWq[idx] = cW2[blk * NPAIR + q];
    }

    // ---- GEMM: u_hat[2 rows][26 cols] in 26 f32x2 accumulators ----
    ull acc[2][NPAIR];
    #pragma unroll
    for (int r = 0; r < 2; r++)
        #pragma unroll
        for (int p = 0; p < NPAIR; p++) acc[r][p] = 0ull;

    const float4* xg = reinterpret_cast<const float4*>(x) + (size_t)b * (INP * KDIM / 4);

    for (int kc = 0; kc < NCHUNK; kc++) {
        __syncthreads();                 // sX safe to overwrite (also orders sW writes)
        const int k0q = kc * (KC / 4);
        #pragma unroll
        for (int it2 = 0; it2 < (INP * (KC / 4)) / THREADS; it2++) {   // 12 float4/thread
            int idx  = t + it2 * THREADS;
            int row  = idx / (KC / 4);
            int slot = idx % (KC / 4);
            float4 v = xg[row * (KDIM / 4) + k0q + slot];
            float* p0 = sX + (2 * slot) * X_STRIDE + (row >> 1) * 4 + (row & 1) * 2;
            *reinterpret_cast<float2*>(p0)            = make_float2(v.x, v.y);  // j2 = 2*slot
            *reinterpret_cast<float2*>(p0 + X_STRIDE) = make_float2(v.z, v.w);  // j2 = 2*slot+1
        }
        __syncthreads();

        const ulonglong2* wb  = cW2 + kc * NJ2 * NPAIR;
        const ulonglong2* swb = sWq + kc * NJ2 * NSMEMQ;
        #pragma unroll
        for (int j2 = 0; j2 < NJ2; j2++) {
            // {x(k0,r0), x(k1,r0), x(k0,r1), x(k1,r1)}
            float4 xv = *reinterpret_cast<const float4*>(sX + j2 * X_STRIDE + t * 4);
            ull a0 = dup2(xv.x);   // k0, row0
            ull a1 = dup2(xv.y);   // k1, row0
            ull b0 = dup2(xv.z);   // k0, row1
            ull b1 = dup2(xv.w);   // k1, row1

            const ulonglong2* wq  = wb  + j2 * NPAIR;
            const ulonglong2* swq = swb + j2 * NSMEMQ;

            // q = 0..4 from SMEM broadcast (k0 pairs 2q, 2q+1)
            #pragma unroll
            for (int q = 0; q < NSMEMQ; q++) {
                ulonglong2 v = swq[q];                       // uniform addr -> LDS.128 bcast
                ffma2(acc[0][2 * q],     a0, v.x);
                ffma2(acc[1][2 * q],     b0, v.x);
                ffma2(acc[0][2 * q + 1], a0, v.y);
                ffma2(acc[1][2 * q + 1], b0, v.y);
            }
            // q = 5 from const (k0 pairs 10, 11)
            {
                ulonglong2 v = wq[5];
                ffma2(acc[0][10], a0, v.x);
                ffma2(acc[1][10], b0, v.x);
                ffma2(acc[0][11], a0, v.y);
                ffma2(acc[1][11], b0, v.y);
            }
            // q = 6 : k0 pair 12, k1 pair 0
            {
                ulonglong2 v = wq[6];
                ffma2(acc[0][12], a0, v.x);
                ffma2(acc[1][12], b0, v.x);
                ffma2(acc[0][0],  a1, v.y);
                ffma2(acc[1][0],  b1, v.y);
            }
            // q = 7..12 : k1 pairs (2q-13, 2q-12)
            #pragma unroll
            for (int q = 7; q < 13; q++) {
                ulonglong2 v = wq[q];
                ffma2(acc[0][2 * q - 13], a1, v.x);
                ffma2(acc[1][2 * q - 13], b1, v.x);
                ffma2(acc[0][2 * q - 12], a1, v.y);
                ffma2(acc[1][2 * q - 12], b1, v.y);
            }
        }
    }
    __syncthreads();

    // ---- unpack u_hat ----
    float u[2][26];
    #pragma unroll
    for (int r = 0; r < 2; r++)
        #pragma unroll
        for (int p = 0; p < NPAIR; p++)
            unpack2(acc[r][p], u[r][2 * p], u[r][2 * p + 1]);

    float bb[2][5];
    #pragma unroll
    for (int r = 0; r < 2; r++)
        #pragma unroll
        for (int i = 0; i < 5; i++) bb[r][i] = 0.f;

    // ---- 4 routing iterations (verbatim from validated kernel) ----
    for (int it = 0; it < 4; it++) {
        float cw[2][5];
        #pragma unroll
        for (int r = 0; r < 2; r++) {
            float m = bb[r][0];
            #pragma unroll
            for (int i = 1; i < 5; i++) m = fmaxf(m, bb[r][i]);
            float e[5], s = 0.f;
            #pragma unroll
            for (int i = 0; i < 5; i++) { e[i] = __expf(bb[r][i] - m); s += e[i]; }
            float inv = 1.f / s;
            #pragma unroll
            for (int i = 0; i < 5; i++) cw[r][i] = e[i] * inv;
        }
        #pragma unroll
        for (int c = 0; c < 25; c++)
            scratch[t * SCR_STRIDE + c] = cw[0][c / 5] * u[0][c] + cw[1][c / 5] * u[1][c];
        __syncthreads();
        if (lane < 25) {
            float s = 0.f;
            #pragma unroll
            for (int uu = 0; uu < 32; uu++) s += scratch[(g * 32 + uu) * SCR_STRIDE + lane];
            red[g * 26 + lane] = s;
        }
        __syncthreads();
        if (t < 25) {
            float s = 0.f;
            #pragma unroll
            for (int gg = 0; gg < 8; gg++) s += red[gg * 26 + t];
            raw[t] = s;
        }
        __syncthreads();
        if (t < 25) {
            int i5 = (t / 5) * 5;
            float sq = 0.f;
            #pragma unroll
            for (int k = 0; k < 5; k++) { float v = raw[i5 + k]; sq += v * v; }
            sOut[t] = raw[t] * rsqrtf(sq + 1e-7f);   // squash = pure norm-normalization
        }
        __syncthreads();
        if (it < 3) {
            float ov[25];
            #pragma unroll
            for (int c = 0; c < 25; c++) ov[c] = sOut[c];
            #pragma unroll
            for (int r = 0; r < 2; r++)
                #pragma unroll
                for (int i = 0; i < 5; i++) {
                    float s = 0.f;
                    #pragma unroll
                    for (int k = 0; k < 5; k++) s += ov[i * 5 + k] * u[r][i * 5 + k];
                    bb[r][i] = s;   // b REPLACED each iteration (matches reference)
                }
        }
    }

    if (t < 25) out[b * 25 + t] = sOut[t];
}

extern "C" void kernel_launch(void* const* d_in, const int* in_sizes, int n_in,
                              void* d_out, int out_size)
{
    const float* x = (const float*)d_in[0];
    const float* W = (const float*)d_in[1];
    float* out = (float*)d_out;

    // Pack W[120][25] -> constant [120][26] floats (col 25 stays 0 from static init).
    void* csym = nullptr;
    cudaGetSymbolAddress(&csym, cW2);
    cudaMemcpy2DAsync(csym, 26 * sizeof(float),
                      W, 25 * sizeof(float),
                      25 * sizeof(float), KDIM,
                      cudaMemcpyDeviceToDevice, 0);

    cudaFuncSetAttribute(caps_kernel, cudaFuncAttributeMaxDynamicSharedMemorySize, SMEM_BYTES);
    caps_kernel<<<1024, THREADS, SMEM_BYTES>>>(x, out);
}